// round 2
// baseline (speedup 1.0000x reference)
#include <cuda_runtime.h>

#define BB 2
#define SS 2048
#define DD 2048
#define HH 8
#define DKK 256
#define SCALING 0.0625f
#define NEGV (-1e9f)

// Scratch (device globals; no allocation allowed)
__device__ float g_Q[(size_t)BB * SS * DD];
__device__ float g_K[(size_t)BB * SS * DD];
__device__ float g_V[(size_t)BB * SS * DD];
__device__ float g_score[BB * HH * SS];
__device__ float g_pool[BB * DD];

// ---------------------------------------------------------------------------
// C[m,n] = sum_k A[m,k] * W[n,k] + bias[n]   (NT GEMM, both K-major)
// 128x128 block tile, BK=8, 256 threads, 8x8 micro-tile (split 4+4).
// ---------------------------------------------------------------------------
__global__ void __launch_bounds__(256) gemm128_nt_bias(
    const float* __restrict__ A, const float* __restrict__ W,
    const float* __restrict__ bias, float* __restrict__ C,
    int M, int N, int K)
{
    __shared__ float As[8][128];
    __shared__ float Ws[8][128];
    const int bm = blockIdx.y * 128;
    const int bn = blockIdx.x * 128;
    const int tid = threadIdx.x;
    const int tx = tid & 15, ty = tid >> 4;
    const int lr = tid >> 1;            // 0..127 row of tile
    const int lc = (tid & 1) * 4;       // 0 or 4 (k offset)

    float acc[8][8];
#pragma unroll
    for (int i = 0; i < 8; i++)
#pragma unroll
        for (int j = 0; j < 8; j++) acc[i][j] = 0.f;

    for (int k0 = 0; k0 < K; k0 += 8) {
        float4 a = *reinterpret_cast<const float4*>(A + (size_t)(bm + lr) * K + k0 + lc);
        float4 w = *reinterpret_cast<const float4*>(W + (size_t)(bn + lr) * K + k0 + lc);
        As[lc + 0][lr] = a.x; As[lc + 1][lr] = a.y; As[lc + 2][lr] = a.z; As[lc + 3][lr] = a.w;
        Ws[lc + 0][lr] = w.x; Ws[lc + 1][lr] = w.y; Ws[lc + 2][lr] = w.z; Ws[lc + 3][lr] = w.w;
        __syncthreads();
#pragma unroll
        for (int k = 0; k < 8; k++) {
            float4 a0 = *reinterpret_cast<const float4*>(&As[k][ty * 4]);
            float4 a1 = *reinterpret_cast<const float4*>(&As[k][64 + ty * 4]);
            float4 b0 = *reinterpret_cast<const float4*>(&Ws[k][tx * 4]);
            float4 b1 = *reinterpret_cast<const float4*>(&Ws[k][64 + tx * 4]);
            float am[8] = {a0.x, a0.y, a0.z, a0.w, a1.x, a1.y, a1.z, a1.w};
            float wn[8] = {b0.x, b0.y, b0.z, b0.w, b1.x, b1.y, b1.z, b1.w};
#pragma unroll
            for (int i = 0; i < 8; i++)
#pragma unroll
                for (int j = 0; j < 8; j++) acc[i][j] += am[i] * wn[j];
        }
        __syncthreads();
    }
#pragma unroll
    for (int i = 0; i < 8; i++) {
        int m = bm + ((i < 4) ? (ty * 4 + i) : (64 + ty * 4 + i - 4));
#pragma unroll
        for (int j = 0; j < 8; j++) {
            int n = bn + ((j < 4) ? (tx * 4 + j) : (64 + tx * 4 + j - 4));
            C[(size_t)m * N + n] = acc[i][j] + bias[n];
        }
    }
}

// ---------------------------------------------------------------------------
// score[b,h,i] = SCALING * ( sum_j leaky_relu(q_i . k_j, 0.1) * Wa[j] + ba )
// One block per (b, h, 64-row i-tile). j streamed in 64-tiles, dk in 16-tiles.
// Never materializes the SxS matrix.
// ---------------------------------------------------------------------------
__global__ void __launch_bounds__(256) score_kernel(
    const float* __restrict__ Q, const float* __restrict__ Kb,
    const float* __restrict__ Wa, const float* __restrict__ ba,
    float* __restrict__ score)
{
    const int b = blockIdx.z, h = blockIdx.y;
    const int i0 = blockIdx.x * 64;
    const float* Qh = Q + (size_t)b * SS * DD + h * DKK;
    const float* Kh = Kb + (size_t)b * SS * DD + h * DKK;

    __shared__ float Qs[16][65];
    __shared__ float Ks[16][65];

    const int tid = threadIdx.x;
    const int tx = tid & 15, ty = tid >> 4;
    const int lr = tid >> 2;           // 0..63
    const int lc = (tid & 3) * 4;      // 0,4,8,12

    float racc[4] = {0.f, 0.f, 0.f, 0.f};

    for (int j0 = 0; j0 < SS; j0 += 64) {
        float acc[4][4];
#pragma unroll
        for (int i = 0; i < 4; i++)
#pragma unroll
            for (int j = 0; j < 4; j++) acc[i][j] = 0.f;

        for (int dk0 = 0; dk0 < DKK; dk0 += 16) {
            float4 a = *reinterpret_cast<const float4*>(Qh + (size_t)(i0 + lr) * DD + dk0 + lc);
            float4 c = *reinterpret_cast<const float4*>(Kh + (size_t)(j0 + lr) * DD + dk0 + lc);
            Qs[lc + 0][lr] = a.x; Qs[lc + 1][lr] = a.y; Qs[lc + 2][lr] = a.z; Qs[lc + 3][lr] = a.w;
            Ks[lc + 0][lr] = c.x; Ks[lc + 1][lr] = c.y; Ks[lc + 2][lr] = c.z; Ks[lc + 3][lr] = c.w;
            __syncthreads();
#pragma unroll
            for (int k = 0; k < 16; k++) {
                float am[4], wn[4];
#pragma unroll
                for (int i = 0; i < 4; i++) am[i] = Qs[k][ty * 4 + i];
#pragma unroll
                for (int j = 0; j < 4; j++) wn[j] = Ks[k][tx * 4 + j];
#pragma unroll
                for (int i = 0; i < 4; i++)
#pragma unroll
                    for (int j = 0; j < 4; j++) acc[i][j] += am[i] * wn[j];
            }
            __syncthreads();
        }
        // epilogue: leaky_relu then weight by Wa[j], fold into per-i accumulator
#pragma unroll
        for (int j = 0; j < 4; j++) {
            float waj = Wa[j0 + tx * 4 + j];
#pragma unroll
            for (int i = 0; i < 4; i++) {
                float e = acc[i][j];
                e = (e >= 0.f) ? e : 0.1f * e;
                racc[i] += e * waj;
            }
        }
    }
    // reduce over the 16 tx lanes (each group of 16 lanes shares the same ty)
#pragma unroll
    for (int i = 0; i < 4; i++) {
        float v = racc[i];
#pragma unroll
        for (int o = 8; o >= 1; o >>= 1) v += __shfl_xor_sync(0xffffffffu, v, o);
        if (tx == 0)
            score[((size_t)b * HH + h) * SS + i0 + ty * 4 + i] = SCALING * (v + ba[0]);
    }
}

// ---------------------------------------------------------------------------
// Masked softmax over the token axis, in-place on score rows of length S.
// ---------------------------------------------------------------------------
__global__ void __launch_bounds__(256) softmax_kernel(float* __restrict__ score,
                                                      const int* __restrict__ mask)
{
    float* row = score + (size_t)blockIdx.x * SS;
    __shared__ float red[256];
    const int tid = threadIdx.x;

    float mx = -3.4e38f;
    for (int i = tid; i < SS; i += 256) {
        float v = (mask[i] != 0) ? NEGV : row[i];
        row[i] = v;
        mx = fmaxf(mx, v);
    }
    red[tid] = mx; __syncthreads();
    for (int o = 128; o >= 1; o >>= 1) {
        if (tid < o) red[tid] = fmaxf(red[tid], red[tid + o]);
        __syncthreads();
    }
    mx = red[0];
    __syncthreads();

    float sum = 0.f;
    for (int i = tid; i < SS; i += 256) {
        float e = __expf(row[i] - mx);
        row[i] = e;
        sum += e;
    }
    red[tid] = sum; __syncthreads();
    for (int o = 128; o >= 1; o >>= 1) {
        if (tid < o) red[tid] += red[tid + o];
        __syncthreads();
    }
    float inv = 1.f / red[0];
    for (int i = tid; i < SS; i += 256) row[i] *= inv;
}

__global__ void zero_kernel(float* __restrict__ p)
{
    int i = blockIdx.x * blockDim.x + threadIdx.x;
    if (i < BB * DD) p[i] = 0.f;
}

// pooled[b, h*DK + d] = sum_i attn[b,h,i] * V[b, i, h*DK + d]
__global__ void __launch_bounds__(256) pool_kernel(
    const float* __restrict__ V, const float* __restrict__ attn,
    float* __restrict__ pooled)
{
    const int b = blockIdx.z, h = blockIdx.y;
    const int d = threadIdx.x;                      // 0..255 (= DK)
    const int i0 = blockIdx.x * 128;
    const float* Vh = V + (size_t)b * SS * DD + h * DKK + d;
    const float* a = attn + ((size_t)b * HH + h) * SS;
    float acc = 0.f;
#pragma unroll 4
    for (int i = i0; i < i0 + 128; i++) acc += a[i] * Vh[(size_t)i * DD];
    atomicAdd(&pooled[(size_t)b * DD + h * DKK + d], acc);
}

// out[b,n] = tanh( sum_k pooled[b,k] * Wp[n,k] + bp[n] )  -- one warp per (b,n)
__global__ void __launch_bounds__(256) final_kernel(
    const float* __restrict__ pooled, const float* __restrict__ Wp,
    const float* __restrict__ bp, float* __restrict__ out)
{
    const int warp = (blockIdx.x * blockDim.x + threadIdx.x) >> 5;
    const int lane = threadIdx.x & 31;
    const int b = warp >> 11;           // / 2048
    const int n = warp & 2047;
    const float* wrow = Wp + (size_t)n * DD;
    const float* prow = pooled + (size_t)b * DD;
    float acc = 0.f;
    for (int k = lane * 4; k < DD; k += 128) {
        float4 w = *reinterpret_cast<const float4*>(wrow + k);
        float4 p = *reinterpret_cast<const float4*>(prow + k);
        acc += w.x * p.x + w.y * p.y + w.z * p.z + w.w * p.w;
    }
#pragma unroll
    for (int o = 16; o >= 1; o >>= 1) acc += __shfl_xor_sync(0xffffffffu, acc, o);
    if (lane == 0) out[(size_t)b * DD + n] = tanhf(acc + bp[n]);
}

extern "C" void kernel_launch(void* const* d_in, const int* in_sizes, int n_in,
                              void* d_out, int out_size)
{
    const float* x    = (const float*)d_in[0];
    const int*   xmsk = (const int*)  d_in[1];
    const float* Wq   = (const float*)d_in[2];
    const float* bq   = (const float*)d_in[3];
    const float* Wk   = (const float*)d_in[4];
    const float* bk   = (const float*)d_in[5];
    const float* Wv   = (const float*)d_in[6];
    const float* bv   = (const float*)d_in[7];
    const float* Wa   = (const float*)d_in[8];
    const float* ba   = (const float*)d_in[9];
    const float* Wp   = (const float*)d_in[10];
    const float* bp   = (const float*)d_in[11];
    float* out = (float*)d_out;

    float *Qp, *Kp, *Vp, *Sp, *Pp;
    cudaGetSymbolAddress((void**)&Qp, g_Q);
    cudaGetSymbolAddress((void**)&Kp, g_K);
    cudaGetSymbolAddress((void**)&Vp, g_V);
    cudaGetSymbolAddress((void**)&Sp, g_score);
    cudaGetSymbolAddress((void**)&Pp, g_pool);

    dim3 gq(DD / 128, (BB * SS) / 128);         // (16, 32)
    gemm128_nt_bias<<<gq, 256>>>(x, Wq, bq, Qp, BB * SS, DD, DD);
    gemm128_nt_bias<<<gq, 256>>>(x, Wk, bk, Kp, BB * SS, DD, DD);
    gemm128_nt_bias<<<gq, 256>>>(x, Wv, bv, Vp, BB * SS, DD, DD);

    score_kernel<<<dim3(SS / 64, HH, BB), 256>>>(Qp, Kp, Wa, ba, Sp);
    softmax_kernel<<<BB * HH, 256>>>(Sp, xmsk);

    zero_kernel<<<(BB * DD + 255) / 256, 256>>>(Pp);
    pool_kernel<<<dim3(SS / 128, HH, BB), 256>>>(Vp, Sp, Pp);
    final_kernel<<<(BB * DD) / 8, 256>>>(Pp, Wp, bp, out);
}

// round 3
// speedup vs baseline: 1.0006x; 1.0006x over previous
#include <cuda_runtime.h>

#define BB 2
#define SS 2048
#define DD 2048
#define HH 8
#define DKK 256
#define SCALING 0.0625f
#define NEGV (-1e9f)

// Scratch (device globals; no allocation allowed)
__device__ float g_Q[(size_t)BB * SS * DD];
__device__ float g_K[(size_t)BB * SS * DD];
__device__ float g_V[(size_t)BB * SS * DD];
__device__ float g_score[BB * HH * SS];
__device__ float g_pool[BB * DD];

// ---------------------------------------------------------------------------
// C[m,n] = sum_k A[m,k] * W[n,k] + bias[n]   (NT GEMM, both K-major)
// 128x128 block tile, BK=8, 256 threads, 8x8 micro-tile (split 4+4).
// ---------------------------------------------------------------------------
__global__ void __launch_bounds__(256) gemm128_nt_bias(
    const float* __restrict__ A, const float* __restrict__ W,
    const float* __restrict__ bias, float* __restrict__ C,
    int M, int N, int K)
{
    __shared__ float As[8][128];
    __shared__ float Ws[8][128];
    const int bm = blockIdx.y * 128;
    const int bn = blockIdx.x * 128;
    const int tid = threadIdx.x;
    const int tx = tid & 15, ty = tid >> 4;
    const int lr = tid >> 1;            // 0..127 row of tile
    const int lc = (tid & 1) * 4;       // 0 or 4 (k offset)

    float acc[8][8];
#pragma unroll
    for (int i = 0; i < 8; i++)
#pragma unroll
        for (int j = 0; j < 8; j++) acc[i][j] = 0.f;

    for (int k0 = 0; k0 < K; k0 += 8) {
        float4 a = *reinterpret_cast<const float4*>(A + (size_t)(bm + lr) * K + k0 + lc);
        float4 w = *reinterpret_cast<const float4*>(W + (size_t)(bn + lr) * K + k0 + lc);
        As[lc + 0][lr] = a.x; As[lc + 1][lr] = a.y; As[lc + 2][lr] = a.z; As[lc + 3][lr] = a.w;
        Ws[lc + 0][lr] = w.x; Ws[lc + 1][lr] = w.y; Ws[lc + 2][lr] = w.z; Ws[lc + 3][lr] = w.w;
        __syncthreads();
#pragma unroll
        for (int k = 0; k < 8; k++) {
            float4 a0 = *reinterpret_cast<const float4*>(&As[k][ty * 4]);
            float4 a1 = *reinterpret_cast<const float4*>(&As[k][64 + ty * 4]);
            float4 b0 = *reinterpret_cast<const float4*>(&Ws[k][tx * 4]);
            float4 b1 = *reinterpret_cast<const float4*>(&Ws[k][64 + tx * 4]);
            float am[8] = {a0.x, a0.y, a0.z, a0.w, a1.x, a1.y, a1.z, a1.w};
            float wn[8] = {b0.x, b0.y, b0.z, b0.w, b1.x, b1.y, b1.z, b1.w};
#pragma unroll
            for (int i = 0; i < 8; i++)
#pragma unroll
                for (int j = 0; j < 8; j++) acc[i][j] += am[i] * wn[j];
        }
        __syncthreads();
    }
#pragma unroll
    for (int i = 0; i < 8; i++) {
        int m = bm + ((i < 4) ? (ty * 4 + i) : (64 + ty * 4 + i - 4));
#pragma unroll
        for (int j = 0; j < 8; j++) {
            int n = bn + ((j < 4) ? (tx * 4 + j) : (64 + tx * 4 + j - 4));
            C[(size_t)m * N + n] = acc[i][j] + bias[n];
        }
    }
}

// ---------------------------------------------------------------------------
// score[b,h,i] = SCALING * ( sum_j leaky_relu(q_i . k_j, 0.1) * Wa[j] + ba )
// One block per (b, h, 64-row i-tile). j streamed in 64-tiles, dk in 16-tiles.
// Never materializes the SxS matrix.
// ---------------------------------------------------------------------------
__global__ void __launch_bounds__(256) score_kernel(
    const float* __restrict__ Q, const float* __restrict__ Kb,
    const float* __restrict__ Wa, const float* __restrict__ ba,
    float* __restrict__ score)
{
    const int b = blockIdx.z, h = blockIdx.y;
    const int i0 = blockIdx.x * 64;
    const float* Qh = Q + (size_t)b * SS * DD + h * DKK;
    const float* Kh = Kb + (size_t)b * SS * DD + h * DKK;

    __shared__ float Qs[16][65];
    __shared__ float Ks[16][65];

    const int tid = threadIdx.x;
    const int tx = tid & 15, ty = tid >> 4;
    const int lr = tid >> 2;           // 0..63
    const int lc = (tid & 3) * 4;      // 0,4,8,12

    float racc[4] = {0.f, 0.f, 0.f, 0.f};

    for (int j0 = 0; j0 < SS; j0 += 64) {
        float acc[4][4];
#pragma unroll
        for (int i = 0; i < 4; i++)
#pragma unroll
            for (int j = 0; j < 4; j++) acc[i][j] = 0.f;

        for (int dk0 = 0; dk0 < DKK; dk0 += 16) {
            float4 a = *reinterpret_cast<const float4*>(Qh + (size_t)(i0 + lr) * DD + dk0 + lc);
            float4 c = *reinterpret_cast<const float4*>(Kh + (size_t)(j0 + lr) * DD + dk0 + lc);
            Qs[lc + 0][lr] = a.x; Qs[lc + 1][lr] = a.y; Qs[lc + 2][lr] = a.z; Qs[lc + 3][lr] = a.w;
            Ks[lc + 0][lr] = c.x; Ks[lc + 1][lr] = c.y; Ks[lc + 2][lr] = c.z; Ks[lc + 3][lr] = c.w;
            __syncthreads();
#pragma unroll
            for (int k = 0; k < 16; k++) {
                float am[4], wn[4];
#pragma unroll
                for (int i = 0; i < 4; i++) am[i] = Qs[k][ty * 4 + i];
#pragma unroll
                for (int j = 0; j < 4; j++) wn[j] = Ks[k][tx * 4 + j];
#pragma unroll
                for (int i = 0; i < 4; i++)
#pragma unroll
                    for (int j = 0; j < 4; j++) acc[i][j] += am[i] * wn[j];
            }
            __syncthreads();
        }
        // epilogue: leaky_relu then weight by Wa[j], fold into per-i accumulator
#pragma unroll
        for (int j = 0; j < 4; j++) {
            float waj = Wa[j0 + tx * 4 + j];
#pragma unroll
            for (int i = 0; i < 4; i++) {
                float e = acc[i][j];
                e = (e >= 0.f) ? e : 0.1f * e;
                racc[i] += e * waj;
            }
        }
    }
    // reduce over the 16 tx lanes (each group of 16 lanes shares the same ty)
#pragma unroll
    for (int i = 0; i < 4; i++) {
        float v = racc[i];
#pragma unroll
        for (int o = 8; o >= 1; o >>= 1) v += __shfl_xor_sync(0xffffffffu, v, o);
        if (tx == 0)
            score[((size_t)b * HH + h) * SS + i0 + ty * 4 + i] = SCALING * (v + ba[0]);
    }
}

// ---------------------------------------------------------------------------
// Masked softmax over the token axis, in-place on score rows of length S.
// ---------------------------------------------------------------------------
__global__ void __launch_bounds__(256) softmax_kernel(float* __restrict__ score,
                                                      const int* __restrict__ mask)
{
    float* row = score + (size_t)blockIdx.x * SS;
    __shared__ float red[256];
    const int tid = threadIdx.x;

    float mx = -3.4e38f;
    for (int i = tid; i < SS; i += 256) {
        float v = (mask[i] != 0) ? NEGV : row[i];
        row[i] = v;
        mx = fmaxf(mx, v);
    }
    red[tid] = mx; __syncthreads();
    for (int o = 128; o >= 1; o >>= 1) {
        if (tid < o) red[tid] = fmaxf(red[tid], red[tid + o]);
        __syncthreads();
    }
    mx = red[0];
    __syncthreads();

    float sum = 0.f;
    for (int i = tid; i < SS; i += 256) {
        float e = __expf(row[i] - mx);
        row[i] = e;
        sum += e;
    }
    red[tid] = sum; __syncthreads();
    for (int o = 128; o >= 1; o >>= 1) {
        if (tid < o) red[tid] += red[tid + o];
        __syncthreads();
    }
    float inv = 1.f / red[0];
    for (int i = tid; i < SS; i += 256) row[i] *= inv;
}

__global__ void zero_kernel(float* __restrict__ p)
{
    int i = blockIdx.x * blockDim.x + threadIdx.x;
    if (i < BB * DD) p[i] = 0.f;
}

// pooled[b, h*DK + d] = sum_i attn[b,h,i] * V[b, i, h*DK + d]
__global__ void __launch_bounds__(256) pool_kernel(
    const float* __restrict__ V, const float* __restrict__ attn,
    float* __restrict__ pooled)
{
    const int b = blockIdx.z, h = blockIdx.y;
    const int d = threadIdx.x;                      // 0..255 (= DK)
    const int i0 = blockIdx.x * 128;
    const float* Vh = V + (size_t)b * SS * DD + h * DKK + d;
    const float* a = attn + ((size_t)b * HH + h) * SS;
    float acc = 0.f;
#pragma unroll 4
    for (int i = i0; i < i0 + 128; i++) acc += a[i] * Vh[(size_t)i * DD];
    atomicAdd(&pooled[(size_t)b * DD + h * DKK + d], acc);
}

// out[b,n] = tanh( sum_k pooled[b,k] * Wp[n,k] + bp[n] )  -- one warp per (b,n)
__global__ void __launch_bounds__(256) final_kernel(
    const float* __restrict__ pooled, const float* __restrict__ Wp,
    const float* __restrict__ bp, float* __restrict__ out)
{
    const int warp = (blockIdx.x * blockDim.x + threadIdx.x) >> 5;
    const int lane = threadIdx.x & 31;
    const int b = warp >> 11;           // / 2048
    const int n = warp & 2047;
    const float* wrow = Wp + (size_t)n * DD;
    const float* prow = pooled + (size_t)b * DD;
    float acc = 0.f;
    for (int k = lane * 4; k < DD; k += 128) {
        float4 w = *reinterpret_cast<const float4*>(wrow + k);
        float4 p = *reinterpret_cast<const float4*>(prow + k);
        acc += w.x * p.x + w.y * p.y + w.z * p.z + w.w * p.w;
    }
#pragma unroll
    for (int o = 16; o >= 1; o >>= 1) acc += __shfl_xor_sync(0xffffffffu, acc, o);
    if (lane == 0) out[(size_t)b * DD + n] = tanhf(acc + bp[n]);
}

extern "C" void kernel_launch(void* const* d_in, const int* in_sizes, int n_in,
                              void* d_out, int out_size)
{
    const float* x    = (const float*)d_in[0];
    const int*   xmsk = (const int*)  d_in[1];
    const float* Wq   = (const float*)d_in[2];
    const float* bq   = (const float*)d_in[3];
    const float* Wk   = (const float*)d_in[4];
    const float* bk   = (const float*)d_in[5];
    const float* Wv   = (const float*)d_in[6];
    const float* bv   = (const float*)d_in[7];
    const float* Wa   = (const float*)d_in[8];
    const float* ba   = (const float*)d_in[9];
    const float* Wp   = (const float*)d_in[10];
    const float* bp   = (const float*)d_in[11];
    float* out = (float*)d_out;

    float *Qp, *Kp, *Vp, *Sp, *Pp;
    cudaGetSymbolAddress((void**)&Qp, g_Q);
    cudaGetSymbolAddress((void**)&Kp, g_K);
    cudaGetSymbolAddress((void**)&Vp, g_V);
    cudaGetSymbolAddress((void**)&Sp, g_score);
    cudaGetSymbolAddress((void**)&Pp, g_pool);

    dim3 gq(DD / 128, (BB * SS) / 128);         // (16, 32)
    gemm128_nt_bias<<<gq, 256>>>(x, Wq, bq, Qp, BB * SS, DD, DD);
    gemm128_nt_bias<<<gq, 256>>>(x, Wk, bk, Kp, BB * SS, DD, DD);
    gemm128_nt_bias<<<gq, 256>>>(x, Wv, bv, Vp, BB * SS, DD, DD);

    score_kernel<<<dim3(SS / 64, HH, BB), 256>>>(Qp, Kp, Wa, ba, Sp);
    softmax_kernel<<<BB * HH, 256>>>(Sp, xmsk);

    zero_kernel<<<(BB * DD + 255) / 256, 256>>>(Pp);
    pool_kernel<<<dim3(SS / 128, HH, BB), 256>>>(Vp, Sp, Pp);
    final_kernel<<<(BB * DD) / 8, 256>>>(Pp, Wp, bp, out);
}